// round 15
// baseline (speedup 1.0000x reference)
#include <cuda_runtime.h>

// Shape (N,C,T,V,M) = (256,3,600,25,2), f32
// LDG.128 main streams: each thread owns a float4 = joints v0=(2*tid)%25, v1=v0+1 (mod 25).
// With THREADS=500, 2q advances by 1000 === 0 (mod 25) per iter -> joints fixed per thread.
#define NB      256
#define TT      600
#define VV      25
#define F4_N    22500              // float4 per sample (90000 floats)
#define F2_N    45000              // float2 per sample
#define THREADS 500
#define ITERS   45                 // 22500 / 500
#define NTOT    23040000.0f

__device__ float        g_partial[NB];
__device__ unsigned int g_count;   // zero at load; finalizer rearms each replay

__global__ __launch_bounds__(THREADS, 2)
void loss_fused(const float4* __restrict__ x4, const float4* __restrict__ y4,
                float* __restrict__ out)
{
    const int n   = blockIdx.x;
    const int tid = threadIdx.x;
    const int v0  = (2 * tid) % VV;            // joint of float4 halves .x/.y
    const int v1  = (v0 + 1) % VV;             // joint of halves .z/.w
    const int r   = (2 * tid) / VV;            // base row offset (0..39)
    const bool wrap = (v0 == VV - 1);          // half1 lives in the next row

    const float4* __restrict__ xn = x4 + (size_t)n * F4_N;
    const float4* __restrict__ yn = y4 + (size_t)n * F4_N;
    const float2* __restrict__ x2 = (const float2*)xn;

    __shared__ float sAbs[VV];
    __shared__ float sSq[VV];
    __shared__ bool  sLast;
    if (tid < VV) { sAbs[tid] = 0.0f; sSq[tid] = 0.0f; }
    __syncthreads();

    float accA0 = 0.0f, accS0 = 0.0f;          // joint v0
    float accA1 = 0.0f, accS1 = 0.0f;          // joint v1

    #pragma unroll 5
    for (int j = 0; j < ITERS; ++j) {
        const int q = tid + j * THREADS;       // float4 index within sample

        const float4 a  = __ldg(&xn[q]);
        const float4 yv = __ldcs(&yn[q]);      // read-once stream: evict-first

        const float dx0 = a.x - yv.x;
        const float dy0 = a.y - yv.y;
        accS0 = fmaf(dx0, dx0, accS0);
        accS0 = fmaf(dy0, dy0, accS0);
        const float dx1 = a.z - yv.z;
        const float dy1 = a.w - yv.w;
        accS1 = fmaf(dx1, dx1, accS1);
        accS1 = fmaf(dy1, dy1, accS1);

        const int row0 = r + 40 * j;           // 0..1799
        const int t0   = row0 % TT;
        const int t1   = wrap ? ((row0 + 1) % TT) : t0;

        if (t0 != TT - 1) {                    // diff within channel; OOB guard
            const float2 b = __ldg(&x2[2 * q + VV]);
            accA0 += fabsf(b.x - a.x) + fabsf(b.y - a.y);
        }
        if (t1 != TT - 1) {
            const float2 b = __ldg(&x2[2 * q + VV + 1]);
            accA1 += fabsf(b.x - a.z) + fabsf(b.y - a.w);
        }
    }

    atomicAdd(&sAbs[v0], accA0);   atomicAdd(&sSq[v0], accS0);
    atomicAdd(&sAbs[v1], accA1);   atomicAdd(&sSq[v1], accS1);
    __syncthreads();

    // Warp 0: per-sample combine, publish partial, elect last block
    if (tid < 32) {
        float myAbs = (tid < VV) ? sAbs[tid] : 0.0f;
        float mySq  = (tid < VV) ? sSq[tid]  : 0.0f;

        float tot = myAbs;
        #pragma unroll
        for (int o = 16; o > 0; o >>= 1)
            tot += __shfl_xor_sync(0xffffffffu, tot, o);

        float contrib = myAbs * mySq;
        #pragma unroll
        for (int o = 16; o > 0; o >>= 1)
            contrib += __shfl_xor_sync(0xffffffffu, contrib, o);

        if (tid == 0) {
            g_partial[n] = (float)VV * contrib / tot;
            __threadfence();
            unsigned int prev = atomicAdd(&g_count, 1u);
            sLast = (prev == NB - 1);
        }
    }
    __syncthreads();

    // Last-arriving block: reduce all 256 partials (fixed order -> deterministic)
    if (sLast && tid < 32) {
        __threadfence();
        float val = 0.0f;
        #pragma unroll
        for (int k = 0; k < NB / 32; ++k)
            val += g_partial[tid + k * 32];
        #pragma unroll
        for (int o = 16; o > 0; o >>= 1)
            val += __shfl_xor_sync(0xffffffffu, val, o);
        if (tid == 0) {
            out[0]  = val / NTOT;
            g_count = 0u;            // rearm for next graph replay
            __threadfence();
        }
    }
}

extern "C" void kernel_launch(void* const* d_in, const int* in_sizes, int n_in,
                              void* d_out, int out_size)
{
    (void)in_sizes; (void)n_in; (void)out_size;
    loss_fused<<<NB, THREADS>>>((const float4*)d_in[0],
                                (const float4*)d_in[1],
                                (float*)d_out);
}

// round 17
// speedup vs baseline: 1.0554x; 1.0554x over previous
#include <cuda_runtime.h>

// Shape (N,C,T,V,M) = (256,3,600,25,2), f32
// Final kernel: single pass over x,y (184 MB), fused weighted-loss algebra:
//   loss = (1/Ntot) * sum_n 25 * (sum_v A[n,v]*S[n,v]) / (sum_v A[n,v])
// where A = sum|dx/dt|, S = sum (x-y)^2 per (n, joint). Constant mean divisors
// cancel in the ratio. One block per sample; thread tid owns joint tid%25.
// Finalize fused via last-block-done election (fixed-order, deterministic).
// Measured: 27.3 us steady-state = 6.74 TB/s (~84% of spec HBM) on sm_100a.
#define NB      256
#define CC      3
#define TT      600
#define VV      25
#define ROWS    (CC * TT)          // 1800 rows of 50 floats per sample
#define F2_ROW  VV                 // 25 float2 per row (one float2 per joint)
#define F2_N    (ROWS * F2_ROW)    // 45000 float2 per sample
#define THREADS 500                // multiple of 25 -> fixed joint per thread
#define ROWS_IT (THREADS / VV)     // 20 rows per iteration
#define ITERS   (ROWS / ROWS_IT)   // 90 iterations
#define NTOT    23040000.0f

__device__ float        g_partial[NB];
__device__ unsigned int g_count;     // zero-init at module load; reset by last block

__global__ __launch_bounds__(THREADS, 2)
void loss_fused(const float2* __restrict__ x, const float2* __restrict__ y,
                float* __restrict__ out)
{
    const int n   = blockIdx.x;
    const int tid = threadIdx.x;
    const int v   = tid % VV;
    const int r0  = tid / VV;

    const float2* __restrict__ xn = x + (size_t)n * F2_N;
    const float2* __restrict__ yn = y + (size_t)n * F2_N;

    __shared__ float sAbs[VV];
    __shared__ float sSq[VV];
    __shared__ bool  sLast;
    if (tid < VV) { sAbs[tid] = 0.0f; sSq[tid] = 0.0f; }
    __syncthreads();

    float accA = 0.0f;   // sum |x[t+1]-x[t]|
    float accS = 0.0f;   // sum (x-y)^2

    #pragma unroll 6
    for (int j = 0; j < ITERS; ++j) {
        const int idx = tid + j * THREADS;
        const int row = r0  + j * ROWS_IT;
        const int t   = row % TT;

        const float2 a  = __ldg(&xn[idx]);
        const float2 yv = __ldcs(&yn[idx]);     // read-once stream: evict-first
        const float dx = a.x - yv.x;
        const float dy = a.y - yv.y;
        accS = fmaf(dx, dx, accS);
        accS = fmaf(dy, dy, accS);

        if (t != TT - 1) {                       // diff stays within channel c
            const float2 b = __ldg(&xn[idx + F2_ROW]);
            accA += fabsf(b.x - a.x) + fabsf(b.y - a.y);
        }
    }

    atomicAdd(&sAbs[v], accA);   // 20 threads per joint slot; tail-time only
    atomicAdd(&sSq[v],  accS);
    __syncthreads();

    // Warp 0: per-sample combine, publish partial, elect last block
    if (tid < 32) {
        float myAbs = (tid < VV) ? sAbs[tid] : 0.0f;
        float mySq  = (tid < VV) ? sSq[tid]  : 0.0f;

        float tot = myAbs;
        #pragma unroll
        for (int o = 16; o > 0; o >>= 1)
            tot += __shfl_xor_sync(0xffffffffu, tot, o);

        float contrib = myAbs * mySq;
        #pragma unroll
        for (int o = 16; o > 0; o >>= 1)
            contrib += __shfl_xor_sync(0xffffffffu, contrib, o);

        if (tid == 0) {
            g_partial[n] = (float)VV * contrib / tot;
            __threadfence();
            unsigned int prev = atomicAdd(&g_count, 1u);
            sLast = (prev == NB - 1);
        }
    }
    __syncthreads();

    // Last-arriving block: reduce all 256 partials (fixed order -> deterministic)
    if (sLast && tid < 32) {
        __threadfence();
        float val = 0.0f;
        #pragma unroll
        for (int k = 0; k < NB / 32; ++k)
            val += g_partial[tid + k * 32];
        #pragma unroll
        for (int o = 16; o > 0; o >>= 1)
            val += __shfl_xor_sync(0xffffffffu, val, o);
        if (tid == 0) {
            out[0]  = val / NTOT;
            g_count = 0u;            // rearm for next graph replay
            __threadfence();
        }
    }
}

extern "C" void kernel_launch(void* const* d_in, const int* in_sizes, int n_in,
                              void* d_out, int out_size)
{
    (void)in_sizes; (void)n_in; (void)out_size;
    loss_fused<<<NB, THREADS>>>((const float2*)d_in[0],
                                (const float2*)d_in[1],
                                (float*)d_out);
}